// round 11
// baseline (speedup 1.0000x reference)
#include <cuda_runtime.h>
#include <math.h>

// ---------------------------------------------------------------------------
// EfficientDet (BiFPN W=88, 3 stages, D=4 heads, 90 classes), B=4, img 512.
// Round 10: entire BiFPN (24 sep-convs) in ONE persistent kernel with a
// global software barrier between dependent steps (was 24 launches x ~55us
// of per-launch latency). Heads/laterals unchanged from 4076us best.
// ---------------------------------------------------------------------------

#define NCH 88
#define BATCH 4
#define ATOT 49104
#define REG_BASE 17677440
#define ANC_BASE (17677440+785664)

static const int g_LH[5]   = {64,32,16,8,4};
static const int g_LHW[5]  = {4096,1024,256,64,16};
static const int g_LCI[5]  = {40,80,112,192,320};
static const int g_LOFF[5] = {0,36864,46080,48384,48960};
static const int g_NPB[5]  = {32,8,2,1,1};
static const int g_BASE[5] = {0,1441792,1802240,1892352,1914880};
#define HEADBUF 1920512

// ---------------------------------------------------------------------------
// static scratch
// ---------------------------------------------------------------------------
#define L3N (4*88*64*64)
#define L4N (4*88*32*32)
#define L5N (4*88*16*16)
#define L6N (4*88*8*8)
#define L7N (4*88*4*4)

__device__ float g_P3[L3N]; __device__ float g_P4[L4N]; __device__ float g_P5[L5N];
__device__ float g_P6[L6N]; __device__ float g_P7[L7N];
__device__ float g_Q3[L3N]; __device__ float g_Q4[L4N]; __device__ float g_Q5[L5N];
__device__ float g_Q6[L6N]; __device__ float g_Q7[L7N];
__device__ float g_T4[L4N]; __device__ float g_T5[L5N]; __device__ float g_T6[L6N];
__device__ float g_HA[2*HEADBUF];
__device__ float g_HB[2*HEADBUF];

// global barrier state (monotonic generation; self-consistent across replays)
__device__ unsigned g_barGen;
__device__ unsigned g_barCnt;

__device__ __forceinline__ void gdep() {
#if __CUDA_ARCH__ >= 900
    cudaGridDependencySynchronize();
#endif
}

// ---------------------------------------------------------------------------
// batched pointwise 1x1 (laterals)
// ---------------------------------------------------------------------------
struct PwMap {
    const float* in[5]; const float* wgt[5]; const float* bias[5]; float* out[5];
    int CI[5]; int HW[5]; int npb[5]; int blkOff[6]; int nent;
};

__global__ __launch_bounds__(256) void pw_k(PwMap m)
{
    __shared__ __align__(16) float sw[44*88];
    int tid = threadIdx.x;
    int bx = blockIdx.x;
    int l = 0;
    while (l + 1 < m.nent && bx >= m.blkOff[l+1]) l++;
    int local = bx - m.blkOff[l];
    int npb = m.npb[l];
    int b = local / npb, pixblk = local - b*npb;
    int HW = m.HW[l], CI = m.CI[l];
    int pix = pixblk*128 + (tid & 127);
    int cog = tid >> 7;
    bool pv = pix < HW;
    const float* wgt = m.wgt[l];

    float acc[44];
#pragma unroll
    for (int j = 0; j < 44; j++) acc[j] = __ldg(m.bias[l] + cog*44 + j);

    const float* ibase = m.in[l] + (size_t)b*CI*HW + pix;

    for (int cb = 0; cb < CI; cb += 44) {
        __syncthreads();
        int lim = min(44, CI - cb);
        for (int i = tid; i < 44*88; i += 256) {
            int co = i / 44, cc = i % 44;
            sw[cc*88 + co] = (cc < lim) ? __ldg(&wgt[co*CI + cb + cc]) : 0.f;
        }
        __syncthreads();
        if (pv) {
            int cc = 0;
            for (; cc + 4 <= lim; cc += 4) {
                float va = __ldg(ibase + (size_t)(cb+cc  )*HW);
                float vb = __ldg(ibase + (size_t)(cb+cc+1)*HW);
                float vc = __ldg(ibase + (size_t)(cb+cc+2)*HW);
                float vd = __ldg(ibase + (size_t)(cb+cc+3)*HW);
                const float4* w0 = (const float4*)&sw[(cc  )*88 + cog*44];
                const float4* w1 = (const float4*)&sw[(cc+1)*88 + cog*44];
                const float4* w2 = (const float4*)&sw[(cc+2)*88 + cog*44];
                const float4* w3 = (const float4*)&sw[(cc+3)*88 + cog*44];
#pragma unroll
                for (int q = 0; q < 11; q++) {
                    float4 a4 = w0[q], b4 = w1[q], c4 = w2[q], d4 = w3[q];
                    acc[q*4+0] += a4.x*va + b4.x*vb + c4.x*vc + d4.x*vd;
                    acc[q*4+1] += a4.y*va + b4.y*vb + c4.y*vc + d4.y*vd;
                    acc[q*4+2] += a4.z*va + b4.z*vb + c4.z*vc + d4.z*vd;
                    acc[q*4+3] += a4.w*va + b4.w*vb + c4.w*vc + d4.w*vd;
                }
            }
            for (; cc < lim; cc++) {
                float v = __ldg(ibase + (size_t)(cb + cc)*HW);
                const float4* wq = (const float4*)&sw[cc*88 + cog*44];
#pragma unroll
                for (int q = 0; q < 11; q++) {
                    float4 wv = wq[q];
                    acc[q*4+0] += wv.x*v; acc[q*4+1] += wv.y*v;
                    acc[q*4+2] += wv.z*v; acc[q*4+3] += wv.w*v;
                }
            }
        }
    }
    if (pv) {
        float* ob = m.out[l] + (size_t)b*88*HW + pix;
#pragma unroll
        for (int j = 0; j < 44; j++)
            ob[(size_t)(cog*44 + j)*HW] = acc[j];
    }
}

// ---------------------------------------------------------------------------
// persistent BiFPN: 24 sep-conv steps, global barrier between steps.
// per step: fuse (3 modes) -> depthwise 3x3 -> pointwise 88x88 + ReLU
// ---------------------------------------------------------------------------
#define SP 260
#define CK 22
#define NSTEP 24

struct SepStep {
    const float* x; const float* y; const float* z;
    const float* fw; const float* dww; const float* pww; const float* pwb;
    float* out; int mode; int H; int npb; int nUnits;
};
struct BifAll { SepStep st[NSTEP]; };

__device__ __forceinline__ void gbar()
{
    __threadfence();
    __syncthreads();
    if (threadIdx.x == 0) {
        unsigned g = *(volatile unsigned*)&g_barGen;
        if (atomicAdd(&g_barCnt, 1u) == gridDim.x - 1) {
            g_barCnt = 0;
            __threadfence();
            atomicExch(&g_barGen, g + 1u);
        } else {
            while (*(volatile unsigned*)&g_barGen == g) __nanosleep(64);
        }
        __threadfence();
    }
    __syncthreads();
}

__device__ void sep_unit(const SepStep& s, int u,
                         float* fbuf, float* dwbuf, float* swp)
{
    int H = s.H, W = H, HW = H*W;
    int lw = 31 - __clz((unsigned)W);
    int tid = threadIdx.x;
    int b = u / s.npb, pixblk = u - b*s.npb;
    int p0 = pixblk*128;
    int qlo = max(0, p0 - W - 1);
    int qhi = min(HW, p0 + 128 + W + 1);
    int span = qhi - qlo;
    int mode = s.mode;

    float w0f = fmaxf(__ldg(s.fw + 0), 0.f);
    float w1f = fmaxf(__ldg(s.fw + 1), 0.f);
    float w2f = (mode == 1) ? fmaxf(__ldg(s.fw + 2), 0.f) : 0.f;
    float sn = 1.f / (w0f + w1f + w2f + 1e-4f);

    int px = tid & 127, cog = tid >> 7;
    bool pv = (p0 + px) < HW;

    float acc[44];
#pragma unroll
    for (int j = 0; j < 44; j++) acc[j] = __ldg(s.pwb + cog*44 + j);

    for (int cb = 0; cb < 88; cb += CK) {
        __syncthreads();
        for (int i = tid; i < CK*88; i += 256) {
            int cc = i / 88, co = i - cc*88;
            swp[cc*88 + co] = __ldg(s.pww + co*88 + cb + cc);
        }
        int tot = CK*span;
        for (int i = tid; i < tot; i += 256) {
            int cc = i / span;
            int qq = qlo + (i - cc*span);
            int ch = cb + cc;
            size_t xb = ((size_t)b*88 + ch)*HW;
            int h = qq >> lw, w = qq & (W-1);
            float xv = __ldg(s.x + xb + qq);
            float val;
            if (mode == 0) {
                float yv = __ldg(s.y + ((size_t)b*88 + ch)*(HW>>2)
                                   + (h>>1)*(W>>1) + (w>>1));
                val = (w0f*xv + w1f*yv)*sn;
            } else {
                const float* zp = s.z + ((size_t)b*88 + ch)*((size_t)HW<<2)
                                      + (size_t)(2*h)*(2*W) + 2*w;
                float m4 = fmaxf(fmaxf(__ldg(zp), __ldg(zp+1)),
                                 fmaxf(__ldg(zp+2*W), __ldg(zp+2*W+1)));
                if (mode == 1) {
                    float yv = __ldg(s.y + xb + qq);
                    val = (w0f*xv + w1f*yv + w2f*m4)*sn;
                } else {
                    val = (w0f*xv + w1f*m4)*sn;
                }
            }
            fbuf[cc*SP + (qq - qlo)] = val;
        }
        __syncthreads();
        int v = tid;
#pragma unroll
        for (int r = 0; r < 11; r++, v += 256) {
            int cc = v >> 7, pp = v & 127;
            int p = p0 + pp;
            float sres = 0.f;
            if (p < HW) {
                int h = p >> lw, w = p & (W-1);
                const float* wp = s.dww + (cb + cc)*9;
                const float* fr = &fbuf[cc*SP];
                int qc = p - qlo;
                bool hu = h > 0, hd = h < H-1, wl = w > 0, wr = w < W-1;
                sres = __ldg(wp+4)*fr[qc];
                if (hu) { sres += __ldg(wp+1)*fr[qc-W];
                          if (wl) sres += __ldg(wp+0)*fr[qc-W-1];
                          if (wr) sres += __ldg(wp+2)*fr[qc-W+1]; }
                if (wl)   sres += __ldg(wp+3)*fr[qc-1];
                if (wr)   sres += __ldg(wp+5)*fr[qc+1];
                if (hd) { sres += __ldg(wp+7)*fr[qc+W];
                          if (wl) sres += __ldg(wp+6)*fr[qc+W-1];
                          if (wr) sres += __ldg(wp+8)*fr[qc+W+1]; }
            }
            dwbuf[cc*128 + pp] = sres;
        }
        __syncthreads();
        if (pv) {
#pragma unroll
            for (int cc = 0; cc < CK; cc++) {
                float vv = dwbuf[cc*128 + px];
                const float4* wq = (const float4*)&swp[cc*88 + cog*44];
#pragma unroll
                for (int q = 0; q < 11; q++) {
                    float4 wv = wq[q];
                    acc[q*4+0] += wv.x*vv; acc[q*4+1] += wv.y*vv;
                    acc[q*4+2] += wv.z*vv; acc[q*4+3] += wv.w*vv;
                }
            }
        }
    }
    if (pv) {
        float* ob = s.out + (size_t)b*88*HW + p0 + px;
#pragma unroll
        for (int j = 0; j < 44; j++)
            ob[(size_t)(cog*44 + j)*HW] = fmaxf(acc[j], 0.f);
    }
}

__global__ __launch_bounds__(256) void bifpn_k(BifAll P)
{
    __shared__ __align__(16) float fbuf[CK*SP];
    __shared__ __align__(16) float dwbuf[CK*128];
    __shared__ __align__(16) float swp[CK*88];

    gdep();   // laterals (pw_k output) consumed by step 0

    for (int sidx = 0; sidx < NSTEP; sidx++) {
        const SepStep& st = P.st[sidx];
        for (int u = blockIdx.x; u < st.nUnits; u += gridDim.x)
            sep_unit(st, u, fbuf, dwbuf, swp);
        gbar();
    }
}

// ---------------------------------------------------------------------------
// batched conv3x3, CI=88. 2 pixels x 22 co per thread (44 accumulators).
// 2 blocks/SM (R6 showed 3/SM regresses).
// ---------------------------------------------------------------------------
struct ConvMap {
    const float* in[10]; float* out[10];
    const float* wgt[10]; const float* bias[10];
    int H[10]; int npb[10]; int loff[10];
    int blkOff[11]; int nent;
};

__global__ __launch_bounds__(256, 2) void conv3x3_k(ConvMap m, int CO, int mode,
                                                    int out_ch, float* headOut)
{
    __shared__ __align__(16) float sw[8*88*12];
    int tid = threadIdx.x;
    int bx = blockIdx.x;
    int l = 0;
    while (l + 1 < m.nent && bx >= m.blkOff[l+1]) l++;
    int local = bx - m.blkOff[l];
    int npb = m.npb[l];
    int b = local / npb, pixblk = local - b*npb;
    int H = m.H[l], W = H, HW = H*W;
    int lw = 31 - __clz(W);
    int pairIdx = tid & 63;
    int cog = tid >> 6;
    int px0 = pixblk*128 + pairIdx*2;
    int cb0 = blockIdx.z * 88;
    bool pv = px0 < HW;
    int h = px0 >> lw, w = px0 & (W-1);
    const float* wgt = m.wgt[l];
    const float* bias = m.bias[l];

    float acc[44];
#pragma unroll
    for (int j = 0; j < 22; j++) {
        int co = cb0 + cog*22 + j;
        float bv = (co < CO) ? __ldg(&bias[co]) : 0.f;
        acc[j] = bv; acc[22 + j] = bv;
    }

    gdep();

    const float* ib = m.in[l] + (size_t)b*88*HW;
    bool hu = h > 0, hd = h < H-1, wl = w > 0, wr = w + 2 < W;

    for (int cb = 0; cb < 88; cb += 8) {
        __syncthreads();
        for (int i = tid; i < 88*8*9; i += 256) {
            int co = i / 72; int r = i % 72; int ci = r / 9; int tap = r % 9;
            int gco = cb0 + co;
            sw[(ci*88 + co)*12 + tap] =
                (gco < CO) ? __ldg(&wgt[((size_t)gco*88 + cb + ci)*9 + tap]) : 0.f;
        }
        __syncthreads();
        if (pv) {
            for (int ci = 0; ci < 8; ci++) {
                const float* ip = ib + (size_t)(cb + ci)*HW + px0;
                float tm = (hu && wl) ? ip[-W-1] : 0.f;
                float ta =  hu        ? ip[-W]   : 0.f;
                float tb =  hu        ? ip[-W+1] : 0.f;
                float tc = (hu && wr) ? ip[-W+2] : 0.f;
                float mm =  wl        ? ip[-1]   : 0.f;
                float ma =              ip[0];
                float mb =              ip[1];
                float mc =  wr        ? ip[2]    : 0.f;
                float bm = (hd && wl) ? ip[W-1]  : 0.f;
                float ba =  hd        ? ip[W]    : 0.f;
                float bb =  hd        ? ip[W+1]  : 0.f;
                float bc = (hd && wr) ? ip[W+2]  : 0.f;
                const float* swc = &sw[(ci*88 + cog*22)*12];
#pragma unroll 2
                for (int j = 0; j < 22; j++) {
                    const float4* wq = (const float4*)(swc + j*12);
                    float4 wa = wq[0];
                    float4 wb4 = wq[1];
                    float  w8 = swc[j*12 + 8];
                    acc[j]      += wa.x*tm + wa.y*ta + wa.z*tb
                                 + wa.w*mm + wb4.x*ma + wb4.y*mb
                                 + wb4.z*bm + wb4.w*ba + w8*bb;
                    acc[22 + j] += wa.x*ta + wa.y*tb + wa.z*tc
                                 + wa.w*ma + wb4.x*mb + wb4.y*mc
                                 + wb4.z*ba + wb4.w*bb + w8*bc;
                }
            }
        }
    }

    if (!pv) return;

    if (mode == 0) {
        float* ob = m.out[l] + (size_t)b*88*HW + px0;
#pragma unroll
        for (int j = 0; j < 22; j++) {
            int co = cog*22 + j;
            ob[(size_t)co*HW]     = fmaxf(acc[j], 0.f);
            ob[(size_t)co*HW + 1] = fmaxf(acc[22 + j], 0.f);
        }
    } else {
#pragma unroll 2
        for (int j = 0; j < 22; j++) {
            int co = cb0 + cog*22 + j;
            if (co < CO) {
                int a = co / out_ch, k = co % out_ch;
                float v0 = acc[j], v1 = acc[22 + j];
                if (mode == 2) {
                    v0 = 1.f / (1.f + __expf(-v0));
                    v1 = 1.f / (1.f + __expf(-v1));
                }
                size_t base = ((size_t)b*ATOT + m.loff[l] + (size_t)px0*9 + a)*out_ch + k;
                headOut[base] = v0;
                headOut[base + (size_t)9*out_ch] = v1;
            }
        }
    }
}

// ---------------------------------------------------------------------------
// anchors
// ---------------------------------------------------------------------------
__global__ void anchors_k(float* __restrict__ out)
{
    int i = blockIdx.x*256 + threadIdx.x;
    if (i >= ATOT) return;
    const int off[6]    = {0,36864,46080,48384,48960,49104};
    const int fsA[5]    = {64,32,16,8,4};
    const int strideA[5]= {8,16,32,64,128};
    const int asizeA[5] = {32,64,128,256,512};
    int l = 0;
    while (l < 4 && i >= off[l+1]) l++;
    int j = i - off[l];
    int fs = fsA[l];
    int pix = j / 9, a = j % 9;
    int r = a / 3, sc = a % 3;
    float scale = exp2f((float)sc * (1.f/3.f));
    float sr = (r == 0) ? 0.70710678118654752f : (r == 1 ? 1.f : 1.41421356237309505f);
    float wsz = (float)asizeA[l] * scale / sr;
    float hsz = (float)asizeA[l] * scale * sr;
    int y = pix / fs, x = pix % fs;
    float cx = (x + 0.5f) * (float)strideA[l];
    float cy = (y + 0.5f) * (float)strideA[l];
    out[(size_t)i*4 + 0] = cx - wsz*0.5f;
    out[(size_t)i*4 + 1] = cy - hsz*0.5f;
    out[(size_t)i*4 + 2] = cx + wsz*0.5f;
    out[(size_t)i*4 + 3] = cy + hsz*0.5f;
}

// ---------------------------------------------------------------------------
// PDL launch helper (fallback to plain launch if attribute rejected)
// ---------------------------------------------------------------------------
static inline void launchPDL(const void* fn, dim3 grid, dim3 block, void** args)
{
    cudaLaunchConfig_t cfg = {};
    cfg.gridDim = grid; cfg.blockDim = block;
    cfg.dynamicSmemBytes = 0; cfg.stream = 0;
    cudaLaunchAttribute at[1];
    at[0].id = cudaLaunchAttributeProgrammaticStreamSerialization;
    at[0].val.programmaticStreamSerializationAllowed = 1;
    cfg.attrs = at; cfg.numAttrs = 1;
    if (cudaLaunchKernelExC(&cfg, fn, args) != cudaSuccess) {
        cudaGetLastError();
        cfg.numAttrs = 0;
        cudaLaunchKernelExC(&cfg, fn, args);
    }
}

// ---------------------------------------------------------------------------
// host driver
// ---------------------------------------------------------------------------
extern "C" void kernel_launch(void* const* d_in, const int* in_sizes, int n_in,
                              void* d_out, int out_size)
{
    (void)in_sizes; (void)n_in; (void)out_size;
    const float* c[5]  = { (const float*)d_in[0], (const float*)d_in[3], (const float*)d_in[6],
                           (const float*)d_in[9], (const float*)d_in[12] };
    const float* lw[5] = { (const float*)d_in[1], (const float*)d_in[4], (const float*)d_in[7],
                           (const float*)d_in[10], (const float*)d_in[13] };
    const float* lb[5] = { (const float*)d_in[2], (const float*)d_in[5], (const float*)d_in[8],
                           (const float*)d_in[11], (const float*)d_in[14] };
    const float* bif_dw = (const float*)d_in[15];
    const float* bif_pw = (const float*)d_in[16];
    const float* bif_pb = (const float*)d_in[17];
    const float* bif_f2 = (const float*)d_in[18];
    const float* bif_f3 = (const float*)d_in[19];
    const float* reg_tw = (const float*)d_in[20];
    const float* reg_tb = (const float*)d_in[21];
    const float* reg_ow = (const float*)d_in[22];
    const float* reg_ob = (const float*)d_in[23];
    const float* cls_tw = (const float*)d_in[24];
    const float* cls_tb = (const float*)d_in[25];
    const float* cls_ow = (const float*)d_in[26];
    const float* cls_ob = (const float*)d_in[27];
    float* outp = (float*)d_out;

    float *A[5], *Bq[5], *T4, *T5, *T6, *HA, *HB;
    cudaGetSymbolAddress((void**)&A[0], g_P3);
    cudaGetSymbolAddress((void**)&A[1], g_P4);
    cudaGetSymbolAddress((void**)&A[2], g_P5);
    cudaGetSymbolAddress((void**)&A[3], g_P6);
    cudaGetSymbolAddress((void**)&A[4], g_P7);
    cudaGetSymbolAddress((void**)&Bq[0], g_Q3);
    cudaGetSymbolAddress((void**)&Bq[1], g_Q4);
    cudaGetSymbolAddress((void**)&Bq[2], g_Q5);
    cudaGetSymbolAddress((void**)&Bq[3], g_Q6);
    cudaGetSymbolAddress((void**)&Bq[4], g_Q7);
    cudaGetSymbolAddress((void**)&T4, g_T4);
    cudaGetSymbolAddress((void**)&T5, g_T5);
    cudaGetSymbolAddress((void**)&T6, g_T6);
    cudaGetSymbolAddress((void**)&HA, g_HA);
    cudaGetSymbolAddress((void**)&HB, g_HB);

    // anchors (independent)
    anchors_k<<<(ATOT + 255)/256, 256>>>(outp + ANC_BASE);

    // ---- laterals: one batched launch (reads only graph inputs) ----
    float* cur[5] = { A[0], A[1], A[2], A[3], A[4] };
    {
        PwMap pm; pm.nent = 5;
        int acc = 0;
        for (int l = 0; l < 5; l++) {
            pm.in[l] = c[l]; pm.wgt[l] = lw[l]; pm.bias[l] = lb[l];
            pm.out[l] = cur[l];
            pm.CI[l] = g_LCI[l]; pm.HW[l] = g_LHW[l]; pm.npb[l] = g_NPB[l];
            pm.blkOff[l] = acc; acc += g_NPB[l]*BATCH;
        }
        pm.blkOff[5] = acc;
        pw_k<<<acc, 256>>>(pm);
    }

    // ---- BiFPN: ONE persistent kernel, 24 steps, global barrier between ----
    {
        BifAll P;
        int sidx = 0;
        float* T[5] = { nullptr, T4, T5, T6, nullptr };
        auto add = [&](int idx, int lvl, int mode, const float* x, const float* y,
                       const float* z, const float* fwp,
                       const float* dws, const float* pws, const float* pbs,
                       float* dst) {
            SepStep& st = P.st[sidx++];
            st.x = x; st.y = y; st.z = z; st.fw = fwp;
            st.dww = dws + idx*88*9;
            st.pww = pws + (size_t)idx*88*88;
            st.pwb = pbs + idx*88;
            st.out = dst; st.mode = mode; st.H = g_LH[lvl];
            st.npb = g_NPB[lvl]; st.nUnits = g_NPB[lvl]*BATCH;
        };
        for (int s = 0; s < 3; s++) {
            const float* dws = bif_dw + (size_t)s*8*88*9;
            const float* pws = bif_pw + (size_t)s*8*88*88;
            const float* pbs = bif_pb + (size_t)s*8*88;
            const float* f2  = bif_f2 + (size_t)s*10;
            const float* f3  = bif_f3 + (size_t)s*9;
            auto oth = [&](int l) { return (cur[l] == A[l]) ? Bq[l] : A[l]; };

            add(0, 3, 0, cur[3], cur[4], nullptr, f2 + 0, dws, pws, pbs, T[3]);
            add(1, 2, 0, cur[2], T[3],  nullptr, f2 + 2, dws, pws, pbs, T[2]);
            add(2, 1, 0, cur[1], T[2],  nullptr, f2 + 4, dws, pws, pbs, T[1]);
            float* n0 = oth(0);
            add(3, 0, 0, cur[0], T[1],  nullptr, f2 + 6, dws, pws, pbs, n0); cur[0] = n0;
            float* n1 = oth(1);
            add(4, 1, 1, cur[1], T[1], cur[0], f3 + 0, dws, pws, pbs, n1); cur[1] = n1;
            float* n2 = oth(2);
            add(5, 2, 1, cur[2], T[2], cur[1], f3 + 3, dws, pws, pbs, n2); cur[2] = n2;
            float* n3 = oth(3);
            add(6, 3, 1, cur[3], T[3], cur[2], f3 + 6, dws, pws, pbs, n3); cur[3] = n3;
            float* n4 = oth(4);
            add(7, 4, 2, cur[4], nullptr, cur[3], f2 + 8, dws, pws, pbs, n4); cur[4] = n4;
        }

        // persistent grid: guaranteed-resident block count
        int occ = 0;
        cudaOccupancyMaxActiveBlocksPerMultiprocessor(&occ, bifpn_k, 256, 0);
        int dev = 0; cudaGetDevice(&dev);
        int sms = 0;
        cudaDeviceGetAttribute(&sms, cudaDevAttrMultiProcessorCount, dev);
        int grid = (occ > 0 && sms > 0) ? occ*sms : 128;
        if (grid > 148) grid = 148;   // max useful = 128 work units; cap barrier cost
        void* args[] = { (void*)&P };
        launchPDL((const void*)bifpn_k, dim3(grid,1,1), dim3(256,1,1), args);
    }

    auto launchConv = [&](ConvMap& cm, dim3 grid, int CO, int mode, int out_ch,
                          float* headOut) {
        void* args[] = { (void*)&cm, (void*)&CO, (void*)&mode,
                         (void*)&out_ch, (void*)&headOut };
        launchPDL((const void*)conv3x3_k, grid, dim3(256,1,1), args);
    };

    // ---- heads: towers batched across 5 levels x 2 heads, PDL-chained ----
    for (int i = 0; i < 4; i++) {
        ConvMap cm; cm.nent = 10;
        int acc = 0;
        float* dstbuf = (i & 1) ? HB : HA;
        float* srcbuf = (i & 1) ? HA : HB;
        for (int e = 0; e < 10; e++) {
            int l = e % 5, head = e / 5;
            cm.H[e] = g_LH[l]; cm.npb[e] = g_NPB[l]; cm.loff[e] = 0;
            cm.blkOff[e] = acc; acc += g_NPB[l]*BATCH;
            cm.in[e]  = (i == 0) ? (const float*)cur[l]
                                 : (const float*)(srcbuf + (size_t)head*HEADBUF + g_BASE[l]);
            cm.out[e] = dstbuf + (size_t)head*HEADBUF + g_BASE[l];
            cm.wgt[e]  = (head ? cls_tw : reg_tw) + (size_t)i*88*88*9;
            cm.bias[e] = (head ? cls_tb : reg_tb) + i*88;
        }
        cm.blkOff[10] = acc;
        launchConv(cm, dim3(acc, 1, 1), 88, 0, 0, nullptr);
    }

    // ---- output convs (tower result in HB) ----
    {
        ConvMap cm; cm.nent = 5;
        int acc = 0;
        for (int l = 0; l < 5; l++) {
            cm.H[l] = g_LH[l]; cm.npb[l] = g_NPB[l]; cm.loff[l] = g_LOFF[l];
            cm.blkOff[l] = acc; acc += g_NPB[l]*BATCH;
            cm.in[l] = HB + g_BASE[l];
            cm.out[l] = nullptr;
            cm.wgt[l] = reg_ow; cm.bias[l] = reg_ob;
        }
        cm.blkOff[5] = acc;
        launchConv(cm, dim3(acc, 1, 1), 36, 1, 4, outp + REG_BASE);
    }
    {
        ConvMap cm; cm.nent = 5;
        int acc = 0;
        for (int l = 0; l < 5; l++) {
            cm.H[l] = g_LH[l]; cm.npb[l] = g_NPB[l]; cm.loff[l] = g_LOFF[l];
            cm.blkOff[l] = acc; acc += g_NPB[l]*BATCH;
            cm.in[l] = HB + (size_t)HEADBUF + g_BASE[l];
            cm.out[l] = nullptr;
            cm.wgt[l] = cls_ow; cm.bias[l] = cls_ob;
        }
        cm.blkOff[5] = acc;
        launchConv(cm, dim3(acc, 1, 10), 810, 2, 90, outp);
    }
}

// round 13
// speedup vs baseline: 1.2047x; 1.2047x over previous
#include <cuda_runtime.h>
#include <math.h>

// ---------------------------------------------------------------------------
// EfficientDet (BiFPN W=88, 3 stages, D=4 heads, 90 classes), B=4, img 512.
// Round 11: BiFPN reverted to 24 PDL launches (R10 persistent was neutral).
// conv3x3_k: co-extent per block 88 -> 44 (blockIdx.z), 22 acc/thread,
// 4 blocks/SM (592 slots, 32 warps/SM). Towers: 704 blocks = 1.19 waves.
// ---------------------------------------------------------------------------

#define NCH 88
#define BATCH 4
#define ATOT 49104
#define REG_BASE 17677440
#define ANC_BASE (17677440+785664)

static const int g_LH[5]   = {64,32,16,8,4};
static const int g_LHW[5]  = {4096,1024,256,64,16};
static const int g_LCI[5]  = {40,80,112,192,320};
static const int g_LOFF[5] = {0,36864,46080,48384,48960};
static const int g_NPB[5]  = {32,8,2,1,1};
static const int g_BASE[5] = {0,1441792,1802240,1892352,1914880};
#define HEADBUF 1920512

// ---------------------------------------------------------------------------
// static scratch
// ---------------------------------------------------------------------------
#define L3N (4*88*64*64)
#define L4N (4*88*32*32)
#define L5N (4*88*16*16)
#define L6N (4*88*8*8)
#define L7N (4*88*4*4)

__device__ float g_P3[L3N]; __device__ float g_P4[L4N]; __device__ float g_P5[L5N];
__device__ float g_P6[L6N]; __device__ float g_P7[L7N];
__device__ float g_Q3[L3N]; __device__ float g_Q4[L4N]; __device__ float g_Q5[L5N];
__device__ float g_Q6[L6N]; __device__ float g_Q7[L7N];
__device__ float g_T4[L4N]; __device__ float g_T5[L5N]; __device__ float g_T6[L6N];
__device__ float g_HA[2*HEADBUF];
__device__ float g_HB[2*HEADBUF];

__device__ __forceinline__ void gdep() {
#if __CUDA_ARCH__ >= 900
    cudaGridDependencySynchronize();
#endif
}

// ---------------------------------------------------------------------------
// batched pointwise 1x1 (laterals)
// ---------------------------------------------------------------------------
struct PwMap {
    const float* in[5]; const float* wgt[5]; const float* bias[5]; float* out[5];
    int CI[5]; int HW[5]; int npb[5]; int blkOff[6]; int nent;
};

__global__ __launch_bounds__(256) void pw_k(PwMap m)
{
    __shared__ __align__(16) float sw[44*88];
    int tid = threadIdx.x;
    int bx = blockIdx.x;
    int l = 0;
    while (l + 1 < m.nent && bx >= m.blkOff[l+1]) l++;
    int local = bx - m.blkOff[l];
    int npb = m.npb[l];
    int b = local / npb, pixblk = local - b*npb;
    int HW = m.HW[l], CI = m.CI[l];
    int pix = pixblk*128 + (tid & 127);
    int cog = tid >> 7;
    bool pv = pix < HW;
    const float* wgt = m.wgt[l];

    float acc[44];
#pragma unroll
    for (int j = 0; j < 44; j++) acc[j] = __ldg(m.bias[l] + cog*44 + j);

    const float* ibase = m.in[l] + (size_t)b*CI*HW + pix;

    for (int cb = 0; cb < CI; cb += 44) {
        __syncthreads();
        int lim = min(44, CI - cb);
        for (int i = tid; i < 44*88; i += 256) {
            int co = i / 44, cc = i % 44;
            sw[cc*88 + co] = (cc < lim) ? __ldg(&wgt[co*CI + cb + cc]) : 0.f;
        }
        __syncthreads();
        if (pv) {
            int cc = 0;
            for (; cc + 4 <= lim; cc += 4) {
                float va = __ldg(ibase + (size_t)(cb+cc  )*HW);
                float vb = __ldg(ibase + (size_t)(cb+cc+1)*HW);
                float vc = __ldg(ibase + (size_t)(cb+cc+2)*HW);
                float vd = __ldg(ibase + (size_t)(cb+cc+3)*HW);
                const float4* w0 = (const float4*)&sw[(cc  )*88 + cog*44];
                const float4* w1 = (const float4*)&sw[(cc+1)*88 + cog*44];
                const float4* w2 = (const float4*)&sw[(cc+2)*88 + cog*44];
                const float4* w3 = (const float4*)&sw[(cc+3)*88 + cog*44];
#pragma unroll
                for (int q = 0; q < 11; q++) {
                    float4 a4 = w0[q], b4 = w1[q], c4 = w2[q], d4 = w3[q];
                    acc[q*4+0] += a4.x*va + b4.x*vb + c4.x*vc + d4.x*vd;
                    acc[q*4+1] += a4.y*va + b4.y*vb + c4.y*vc + d4.y*vd;
                    acc[q*4+2] += a4.z*va + b4.z*vb + c4.z*vc + d4.z*vd;
                    acc[q*4+3] += a4.w*va + b4.w*vb + c4.w*vc + d4.w*vd;
                }
            }
            for (; cc < lim; cc++) {
                float v = __ldg(ibase + (size_t)(cb + cc)*HW);
                const float4* wq = (const float4*)&sw[cc*88 + cog*44];
#pragma unroll
                for (int q = 0; q < 11; q++) {
                    float4 wv = wq[q];
                    acc[q*4+0] += wv.x*v; acc[q*4+1] += wv.y*v;
                    acc[q*4+2] += wv.z*v; acc[q*4+3] += wv.w*v;
                }
            }
        }
    }
    if (pv) {
        float* ob = m.out[l] + (size_t)b*88*HW + pix;
#pragma unroll
        for (int j = 0; j < 44; j++)
            ob[(size_t)(cog*44 + j)*HW] = acc[j];
    }
}

// ---------------------------------------------------------------------------
// fused BiFPN sep-conv: fuse -> depthwise 3x3 -> pointwise 88x88 + ReLU
// channel chunk = 22 (4 iterations over 88 channels).
// ---------------------------------------------------------------------------
#define SP 260
#define CK 22

__global__ __launch_bounds__(256) void sep_k(
    const float* __restrict__ x, const float* __restrict__ y,
    const float* __restrict__ z, const float* __restrict__ fw,
    int mode, const float* __restrict__ dww, const float* __restrict__ pww,
    const float* __restrict__ pwb, float* __restrict__ out, int H)
{
    __shared__ __align__(16) float fbuf[CK*SP];
    __shared__ __align__(16) float dwbuf[CK*128];
    __shared__ __align__(16) float swp[CK*88];
    int W = H, HW = H*W;
    int lw = 31 - __clz(W);
    int tid = threadIdx.x;
    int b = blockIdx.y;
    int p0 = blockIdx.x*128;
    int qlo = max(0, p0 - W - 1);
    int qhi = min(HW, p0 + 128 + W + 1);
    int span = qhi - qlo;

    float w0f = fmaxf(__ldg(fw + 0), 0.f);
    float w1f = fmaxf(__ldg(fw + 1), 0.f);
    float w2f = (mode == 1) ? fmaxf(__ldg(fw + 2), 0.f) : 0.f;
    float sn = 1.f / (w0f + w1f + w2f + 1e-4f);

    int px = tid & 127, cog = tid >> 7;
    bool pv = (p0 + px) < HW;

    float acc[44];
#pragma unroll
    for (int j = 0; j < 44; j++) acc[j] = __ldg(pwb + cog*44 + j);

    gdep();

    for (int cb = 0; cb < 88; cb += CK) {
        __syncthreads();
        for (int i = tid; i < CK*88; i += 256) {
            int cc = i / 88, co = i - cc*88;
            swp[cc*88 + co] = __ldg(pww + co*88 + cb + cc);
        }
        int tot = CK*span;
        for (int i = tid; i < tot; i += 256) {
            int cc = i / span;
            int qq = qlo + (i - cc*span);
            int ch = cb + cc;
            size_t xb = ((size_t)b*88 + ch)*HW;
            int h = qq >> lw, w = qq & (W-1);
            float xv = __ldg(x + xb + qq);
            float val;
            if (mode == 0) {
                float yv = __ldg(y + ((size_t)b*88 + ch)*(HW>>2)
                                   + (h>>1)*(W>>1) + (w>>1));
                val = (w0f*xv + w1f*yv)*sn;
            } else {
                const float* zp = z + ((size_t)b*88 + ch)*((size_t)HW<<2)
                                    + (size_t)(2*h)*(2*W) + 2*w;
                float m4 = fmaxf(fmaxf(__ldg(zp), __ldg(zp+1)),
                                 fmaxf(__ldg(zp+2*W), __ldg(zp+2*W+1)));
                if (mode == 1) {
                    float yv = __ldg(y + xb + qq);
                    val = (w0f*xv + w1f*yv + w2f*m4)*sn;
                } else {
                    val = (w0f*xv + w1f*m4)*sn;
                }
            }
            fbuf[cc*SP + (qq - qlo)] = val;
        }
        __syncthreads();
        int v = tid;
#pragma unroll
        for (int r = 0; r < 11; r++, v += 256) {
            int cc = v >> 7, pp = v & 127;
            int p = p0 + pp;
            float sres = 0.f;
            if (p < HW) {
                int h = p >> lw, w = p & (W-1);
                const float* wp = dww + (cb + cc)*9;
                const float* fr = &fbuf[cc*SP];
                int qc = p - qlo;
                bool hu = h > 0, hd = h < H-1, wl = w > 0, wr = w < W-1;
                sres = __ldg(wp+4)*fr[qc];
                if (hu) { sres += __ldg(wp+1)*fr[qc-W];
                          if (wl) sres += __ldg(wp+0)*fr[qc-W-1];
                          if (wr) sres += __ldg(wp+2)*fr[qc-W+1]; }
                if (wl)   sres += __ldg(wp+3)*fr[qc-1];
                if (wr)   sres += __ldg(wp+5)*fr[qc+1];
                if (hd) { sres += __ldg(wp+7)*fr[qc+W];
                          if (wl) sres += __ldg(wp+6)*fr[qc+W-1];
                          if (wr) sres += __ldg(wp+8)*fr[qc+W+1]; }
            }
            dwbuf[cc*128 + pp] = sres;
        }
        __syncthreads();
        if (pv) {
#pragma unroll
            for (int cc = 0; cc < CK; cc++) {
                float vv = dwbuf[cc*128 + px];
                const float4* wq = (const float4*)&swp[cc*88 + cog*44];
#pragma unroll
                for (int q = 0; q < 11; q++) {
                    float4 wv = wq[q];
                    acc[q*4+0] += wv.x*vv; acc[q*4+1] += wv.y*vv;
                    acc[q*4+2] += wv.z*vv; acc[q*4+3] += wv.w*vv;
                }
            }
        }
    }
    if (pv) {
        float* ob = out + (size_t)b*88*HW + p0 + px;
#pragma unroll
        for (int j = 0; j < 44; j++)
            ob[(size_t)(cog*44 + j)*HW] = fmaxf(acc[j], 0.f);
    }
}

// ---------------------------------------------------------------------------
// batched conv3x3, CI=88. 44 co per block via blockIdx.z; per thread:
// 2 pixels x 11 co (22 accumulators). block: 256 thr = 64 pairs x 4 cog.
// 4 blocks/SM -> 592 slots, 32 warps/SM.
// ---------------------------------------------------------------------------
struct ConvMap {
    const float* in[10]; float* out[10];
    const float* wgt[10]; const float* bias[10];
    int H[10]; int npb[10]; int loff[10];
    int blkOff[11]; int nent;
};

__global__ __launch_bounds__(256, 4) void conv3x3_k(ConvMap m, int CO, int mode,
                                                    int out_ch, float* headOut)
{
    __shared__ __align__(16) float sw[8*44*12];   // 16.9 KB
    int tid = threadIdx.x;
    int bx = blockIdx.x;
    int l = 0;
    while (l + 1 < m.nent && bx >= m.blkOff[l+1]) l++;
    int local = bx - m.blkOff[l];
    int npb = m.npb[l];
    int b = local / npb, pixblk = local - b*npb;
    int H = m.H[l], W = H, HW = H*W;
    int lw = 31 - __clz(W);
    int pairIdx = tid & 63;
    int cog = tid >> 6;                  // 0..3 (11 co each)
    int px0 = pixblk*128 + pairIdx*2;
    int cb0 = blockIdx.z * 44;
    bool pv = px0 < HW;
    int h = px0 >> lw, w = px0 & (W-1);
    const float* wgt = m.wgt[l];
    const float* bias = m.bias[l];

    float acc[22];                       // acc[j]=px0, acc[11+j]=px1
#pragma unroll
    for (int j = 0; j < 11; j++) {
        int co = cb0 + cog*11 + j;
        float bv = (co < CO) ? __ldg(&bias[co]) : 0.f;
        acc[j] = bv; acc[11 + j] = bv;
    }

    gdep();

    const float* ib = m.in[l] + (size_t)b*88*HW;
    bool hu = h > 0, hd = h < H-1, wl = w > 0, wr = w + 2 < W;

    for (int cb = 0; cb < 88; cb += 8) {
        __syncthreads();
        for (int i = tid; i < 44*8*9; i += 256) {
            int co = i / 72; int r = i % 72; int ci = r / 9; int tap = r % 9;
            int gco = cb0 + co;
            sw[(ci*44 + co)*12 + tap] =
                (gco < CO) ? __ldg(&wgt[((size_t)gco*88 + cb + ci)*9 + tap]) : 0.f;
        }
        __syncthreads();
        if (pv) {
            for (int ci = 0; ci < 8; ci++) {
                const float* ip = ib + (size_t)(cb + ci)*HW + px0;
                float tm = (hu && wl) ? ip[-W-1] : 0.f;
                float ta =  hu        ? ip[-W]   : 0.f;
                float tb =  hu        ? ip[-W+1] : 0.f;
                float tc = (hu && wr) ? ip[-W+2] : 0.f;
                float mm =  wl        ? ip[-1]   : 0.f;
                float ma =              ip[0];
                float mb =              ip[1];
                float mc =  wr        ? ip[2]    : 0.f;
                float bm = (hd && wl) ? ip[W-1]  : 0.f;
                float ba =  hd        ? ip[W]    : 0.f;
                float bb =  hd        ? ip[W+1]  : 0.f;
                float bc = (hd && wr) ? ip[W+2]  : 0.f;
                const float* swc = &sw[(ci*44 + cog*11)*12];
#pragma unroll
                for (int j = 0; j < 11; j++) {
                    const float4* wq = (const float4*)(swc + j*12);
                    float4 wa = wq[0];
                    float4 wb4 = wq[1];
                    float  w8 = swc[j*12 + 8];
                    acc[j]      += wa.x*tm + wa.y*ta + wa.z*tb
                                 + wa.w*mm + wb4.x*ma + wb4.y*mb
                                 + wb4.z*bm + wb4.w*ba + w8*bb;
                    acc[11 + j] += wa.x*ta + wa.y*tb + wa.z*tc
                                 + wa.w*ma + wb4.x*mb + wb4.y*mc
                                 + wb4.z*ba + wb4.w*bb + w8*bc;
                }
            }
        }
    }

    if (!pv) return;

    if (mode == 0) {
        float* ob = m.out[l] + (size_t)b*88*HW + px0;
#pragma unroll
        for (int j = 0; j < 11; j++) {
            int co = cb0 + cog*11 + j;
            ob[(size_t)co*HW]     = fmaxf(acc[j], 0.f);
            ob[(size_t)co*HW + 1] = fmaxf(acc[11 + j], 0.f);
        }
    } else {
#pragma unroll
        for (int j = 0; j < 11; j++) {
            int co = cb0 + cog*11 + j;
            if (co < CO) {
                int a = co / out_ch, k = co % out_ch;
                float v0 = acc[j], v1 = acc[11 + j];
                if (mode == 2) {
                    v0 = 1.f / (1.f + __expf(-v0));
                    v1 = 1.f / (1.f + __expf(-v1));
                }
                size_t base = ((size_t)b*ATOT + m.loff[l] + (size_t)px0*9 + a)*out_ch + k;
                headOut[base] = v0;
                headOut[base + (size_t)9*out_ch] = v1;
            }
        }
    }
}

// ---------------------------------------------------------------------------
// anchors
// ---------------------------------------------------------------------------
__global__ void anchors_k(float* __restrict__ out)
{
    int i = blockIdx.x*256 + threadIdx.x;
    if (i >= ATOT) return;
    const int off[6]    = {0,36864,46080,48384,48960,49104};
    const int fsA[5]    = {64,32,16,8,4};
    const int strideA[5]= {8,16,32,64,128};
    const int asizeA[5] = {32,64,128,256,512};
    int l = 0;
    while (l < 4 && i >= off[l+1]) l++;
    int j = i - off[l];
    int fs = fsA[l];
    int pix = j / 9, a = j % 9;
    int r = a / 3, sc = a % 3;
    float scale = exp2f((float)sc * (1.f/3.f));
    float sr = (r == 0) ? 0.70710678118654752f : (r == 1 ? 1.f : 1.41421356237309505f);
    float wsz = (float)asizeA[l] * scale / sr;
    float hsz = (float)asizeA[l] * scale * sr;
    int y = pix / fs, x = pix % fs;
    float cx = (x + 0.5f) * (float)strideA[l];
    float cy = (y + 0.5f) * (float)strideA[l];
    out[(size_t)i*4 + 0] = cx - wsz*0.5f;
    out[(size_t)i*4 + 1] = cy - hsz*0.5f;
    out[(size_t)i*4 + 2] = cx + wsz*0.5f;
    out[(size_t)i*4 + 3] = cy + hsz*0.5f;
}

// ---------------------------------------------------------------------------
// PDL launch helper (fallback to plain launch if attribute rejected)
// ---------------------------------------------------------------------------
static inline void launchPDL(const void* fn, dim3 grid, dim3 block, void** args)
{
    cudaLaunchConfig_t cfg = {};
    cfg.gridDim = grid; cfg.blockDim = block;
    cfg.dynamicSmemBytes = 0; cfg.stream = 0;
    cudaLaunchAttribute at[1];
    at[0].id = cudaLaunchAttributeProgrammaticStreamSerialization;
    at[0].val.programmaticStreamSerializationAllowed = 1;
    cfg.attrs = at; cfg.numAttrs = 1;
    if (cudaLaunchKernelExC(&cfg, fn, args) != cudaSuccess) {
        cudaGetLastError();
        cfg.numAttrs = 0;
        cudaLaunchKernelExC(&cfg, fn, args);
    }
}

// ---------------------------------------------------------------------------
// host driver
// ---------------------------------------------------------------------------
extern "C" void kernel_launch(void* const* d_in, const int* in_sizes, int n_in,
                              void* d_out, int out_size)
{
    (void)in_sizes; (void)n_in; (void)out_size;
    const float* c[5]  = { (const float*)d_in[0], (const float*)d_in[3], (const float*)d_in[6],
                           (const float*)d_in[9], (const float*)d_in[12] };
    const float* lw[5] = { (const float*)d_in[1], (const float*)d_in[4], (const float*)d_in[7],
                           (const float*)d_in[10], (const float*)d_in[13] };
    const float* lb[5] = { (const float*)d_in[2], (const float*)d_in[5], (const float*)d_in[8],
                           (const float*)d_in[11], (const float*)d_in[14] };
    const float* bif_dw = (const float*)d_in[15];
    const float* bif_pw = (const float*)d_in[16];
    const float* bif_pb = (const float*)d_in[17];
    const float* bif_f2 = (const float*)d_in[18];
    const float* bif_f3 = (const float*)d_in[19];
    const float* reg_tw = (const float*)d_in[20];
    const float* reg_tb = (const float*)d_in[21];
    const float* reg_ow = (const float*)d_in[22];
    const float* reg_ob = (const float*)d_in[23];
    const float* cls_tw = (const float*)d_in[24];
    const float* cls_tb = (const float*)d_in[25];
    const float* cls_ow = (const float*)d_in[26];
    const float* cls_ob = (const float*)d_in[27];
    float* outp = (float*)d_out;

    float *A[5], *Bq[5], *T4, *T5, *T6, *HA, *HB;
    cudaGetSymbolAddress((void**)&A[0], g_P3);
    cudaGetSymbolAddress((void**)&A[1], g_P4);
    cudaGetSymbolAddress((void**)&A[2], g_P5);
    cudaGetSymbolAddress((void**)&A[3], g_P6);
    cudaGetSymbolAddress((void**)&A[4], g_P7);
    cudaGetSymbolAddress((void**)&Bq[0], g_Q3);
    cudaGetSymbolAddress((void**)&Bq[1], g_Q4);
    cudaGetSymbolAddress((void**)&Bq[2], g_Q5);
    cudaGetSymbolAddress((void**)&Bq[3], g_Q6);
    cudaGetSymbolAddress((void**)&Bq[4], g_Q7);
    cudaGetSymbolAddress((void**)&T4, g_T4);
    cudaGetSymbolAddress((void**)&T5, g_T5);
    cudaGetSymbolAddress((void**)&T6, g_T6);
    cudaGetSymbolAddress((void**)&HA, g_HA);
    cudaGetSymbolAddress((void**)&HB, g_HB);

    // anchors (independent)
    anchors_k<<<(ATOT + 255)/256, 256>>>(outp + ANC_BASE);

    // ---- laterals: one batched launch ----
    float* cur[5] = { A[0], A[1], A[2], A[3], A[4] };
    {
        PwMap pm; pm.nent = 5;
        int acc = 0;
        for (int l = 0; l < 5; l++) {
            pm.in[l] = c[l]; pm.wgt[l] = lw[l]; pm.bias[l] = lb[l];
            pm.out[l] = cur[l];
            pm.CI[l] = g_LCI[l]; pm.HW[l] = g_LHW[l]; pm.npb[l] = g_NPB[l];
            pm.blkOff[l] = acc; acc += g_NPB[l]*BATCH;
        }
        pm.blkOff[5] = acc;
        pw_k<<<acc, 256>>>(pm);
    }

    // ---- BiFPN stages: 8 fused sep-conv launches each, PDL-chained ----
    for (int s = 0; s < 3; s++) {
        const float* dws = bif_dw + (size_t)s*8*88*9;
        const float* pws = bif_pw + (size_t)s*8*88*88;
        const float* pbs = bif_pb + (size_t)s*8*88;
        const float* f2  = bif_f2 + (size_t)s*10;
        const float* f3  = bif_f3 + (size_t)s*9;

        auto sep = [&](int idx, int lvl, int mode, const float* x, const float* y,
                       const float* z, const float* fwp, float* dst) {
            int H = g_LH[lvl];
            dim3 grid((g_LHW[lvl] + 127)/128, BATCH);
            const float* dwwp = dws + idx*88*9;
            const float* pwwp = pws + (size_t)idx*88*88;
            const float* pbp  = pbs + idx*88;
            void* args[] = { (void*)&x, (void*)&y, (void*)&z, (void*)&fwp,
                             (void*)&mode, (void*)&dwwp, (void*)&pwwp,
                             (void*)&pbp, (void*)&dst, (void*)&H };
            launchPDL((const void*)sep_k, grid, dim3(256,1,1), args);
        };
        auto oth = [&](int l) { return (cur[l] == A[l]) ? Bq[l] : A[l]; };

        sep(0, 3, 0, cur[3], cur[4], nullptr, f2 + 0, T6);
        sep(1, 2, 0, cur[2], T6,     nullptr, f2 + 2, T5);
        sep(2, 1, 0, cur[1], T5,     nullptr, f2 + 4, T4);
        float* n0 = oth(0); sep(3, 0, 0, cur[0], T4, nullptr, f2 + 6, n0); cur[0] = n0;
        float* n1 = oth(1); sep(4, 1, 1, cur[1], T4, cur[0], f3 + 0, n1); cur[1] = n1;
        float* n2 = oth(2); sep(5, 2, 1, cur[2], T5, cur[1], f3 + 3, n2); cur[2] = n2;
        float* n3 = oth(3); sep(6, 3, 1, cur[3], T6, cur[2], f3 + 6, n3); cur[3] = n3;
        float* n4 = oth(4); sep(7, 4, 2, cur[4], nullptr, cur[3], f2 + 8, n4); cur[4] = n4;
    }

    auto launchConv = [&](ConvMap& cm, dim3 grid, int CO, int mode, int out_ch,
                          float* headOut) {
        void* args[] = { (void*)&cm, (void*)&CO, (void*)&mode,
                         (void*)&out_ch, (void*)&headOut };
        launchPDL((const void*)conv3x3_k, grid, dim3(256,1,1), args);
    };

    // ---- heads: towers batched across 5 levels x 2 heads, z=2 co-blocks ----
    for (int i = 0; i < 4; i++) {
        ConvMap cm; cm.nent = 10;
        int acc = 0;
        float* dstbuf = (i & 1) ? HB : HA;
        float* srcbuf = (i & 1) ? HA : HB;
        for (int e = 0; e < 10; e++) {
            int l = e % 5, head = e / 5;
            cm.H[e] = g_LH[l]; cm.npb[e] = g_NPB[l]; cm.loff[e] = 0;
            cm.blkOff[e] = acc; acc += g_NPB[l]*BATCH;
            cm.in[e]  = (i == 0) ? (const float*)cur[l]
                                 : (const float*)(srcbuf + (size_t)head*HEADBUF + g_BASE[l]);
            cm.out[e] = dstbuf + (size_t)head*HEADBUF + g_BASE[l];
            cm.wgt[e]  = (head ? cls_tw : reg_tw) + (size_t)i*88*88*9;
            cm.bias[e] = (head ? cls_tb : reg_tb) + i*88;
        }
        cm.blkOff[10] = acc;
        launchConv(cm, dim3(acc, 1, 2), 88, 0, 0, nullptr);
    }

    // ---- output convs (tower result in HB) ----
    {
        ConvMap cm; cm.nent = 5;
        int acc = 0;
        for (int l = 0; l < 5; l++) {
            cm.H[l] = g_LH[l]; cm.npb[l] = g_NPB[l]; cm.loff[l] = g_LOFF[l];
            cm.blkOff[l] = acc; acc += g_NPB[l]*BATCH;
            cm.in[l] = HB + g_BASE[l];
            cm.out[l] = nullptr;
            cm.wgt[l] = reg_ow; cm.bias[l] = reg_ob;
        }
        cm.blkOff[5] = acc;
        launchConv(cm, dim3(acc, 1, 1), 36, 1, 4, outp + REG_BASE);
    }
    {
        ConvMap cm; cm.nent = 5;
        int acc = 0;
        for (int l = 0; l < 5; l++) {
            cm.H[l] = g_LH[l]; cm.npb[l] = g_NPB[l]; cm.loff[l] = g_LOFF[l];
            cm.blkOff[l] = acc; acc += g_NPB[l]*BATCH;
            cm.in[l] = HB + (size_t)HEADBUF + g_BASE[l];
            cm.out[l] = nullptr;
            cm.wgt[l] = cls_ow; cm.bias[l] = cls_ob;
        }
        cm.blkOff[5] = acc;
        launchConv(cm, dim3(acc, 1, 19), 810, 2, 90, outp);
    }
}

// round 16
// speedup vs baseline: 1.3242x; 1.0992x over previous
#include <cuda_runtime.h>
#include <math.h>

// ---------------------------------------------------------------------------
// EfficientDet (BiFPN W=88, 3 stages, D=4 heads, 90 classes), B=4, img 512.
// Round 13: reg-head chain and cls-head chain forked onto two streams
// (event fork/join, graph-capturable) so their serial stages interleave and
// fill the 592 block slots; kills the 1.19-wave tail idle of each stage.
// Everything else identical to R12 best (3451us).
// ---------------------------------------------------------------------------

#define NCH 88
#define BATCH 4
#define ATOT 49104
#define REG_BASE 17677440
#define ANC_BASE (17677440+785664)

static const int g_LH[5]   = {64,32,16,8,4};
static const int g_LHW[5]  = {4096,1024,256,64,16};
static const int g_LCI[5]  = {40,80,112,192,320};
static const int g_LOFF[5] = {0,36864,46080,48384,48960};
static const int g_NPB[5]  = {32,8,2,1,1};
static const int g_BASE[5] = {0,1441792,1802240,1892352,1914880};
#define HEADBUF 1920512

// ---------------------------------------------------------------------------
// static scratch
// ---------------------------------------------------------------------------
#define L3N (4*88*64*64)
#define L4N (4*88*32*32)
#define L5N (4*88*16*16)
#define L6N (4*88*8*8)
#define L7N (4*88*4*4)

__device__ float g_P3[L3N]; __device__ float g_P4[L4N]; __device__ float g_P5[L5N];
__device__ float g_P6[L6N]; __device__ float g_P7[L7N];
__device__ float g_Q3[L3N]; __device__ float g_Q4[L4N]; __device__ float g_Q5[L5N];
__device__ float g_Q6[L6N]; __device__ float g_Q7[L7N];
__device__ float g_T4[L4N]; __device__ float g_T5[L5N]; __device__ float g_T6[L6N];
__device__ float g_HA[2*HEADBUF];
__device__ float g_HB[2*HEADBUF];

__device__ __forceinline__ void gdep() {
#if __CUDA_ARCH__ >= 900
    cudaGridDependencySynchronize();
#endif
}

// ---------------------------------------------------------------------------
// batched pointwise 1x1 (laterals)
// ---------------------------------------------------------------------------
struct PwMap {
    const float* in[5]; const float* wgt[5]; const float* bias[5]; float* out[5];
    int CI[5]; int HW[5]; int npb[5]; int blkOff[6]; int nent;
};

__global__ __launch_bounds__(256) void pw_k(PwMap m)
{
    __shared__ __align__(16) float sw[44*88];
    int tid = threadIdx.x;
    int bx = blockIdx.x;
    int l = 0;
    while (l + 1 < m.nent && bx >= m.blkOff[l+1]) l++;
    int local = bx - m.blkOff[l];
    int npb = m.npb[l];
    int b = local / npb, pixblk = local - b*npb;
    int HW = m.HW[l], CI = m.CI[l];
    int pix = pixblk*128 + (tid & 127);
    int cog = tid >> 7;
    bool pv = pix < HW;
    const float* wgt = m.wgt[l];

    float acc[44];
#pragma unroll
    for (int j = 0; j < 44; j++) acc[j] = __ldg(m.bias[l] + cog*44 + j);

    const float* ibase = m.in[l] + (size_t)b*CI*HW + pix;

    for (int cb = 0; cb < CI; cb += 44) {
        __syncthreads();
        int lim = min(44, CI - cb);
        for (int i = tid; i < 44*88; i += 256) {
            int co = i / 44, cc = i % 44;
            sw[cc*88 + co] = (cc < lim) ? __ldg(&wgt[co*CI + cb + cc]) : 0.f;
        }
        __syncthreads();
        if (pv) {
            int cc = 0;
            for (; cc + 4 <= lim; cc += 4) {
                float va = __ldg(ibase + (size_t)(cb+cc  )*HW);
                float vb = __ldg(ibase + (size_t)(cb+cc+1)*HW);
                float vc = __ldg(ibase + (size_t)(cb+cc+2)*HW);
                float vd = __ldg(ibase + (size_t)(cb+cc+3)*HW);
                const float4* w0 = (const float4*)&sw[(cc  )*88 + cog*44];
                const float4* w1 = (const float4*)&sw[(cc+1)*88 + cog*44];
                const float4* w2 = (const float4*)&sw[(cc+2)*88 + cog*44];
                const float4* w3 = (const float4*)&sw[(cc+3)*88 + cog*44];
#pragma unroll
                for (int q = 0; q < 11; q++) {
                    float4 a4 = w0[q], b4 = w1[q], c4 = w2[q], d4 = w3[q];
                    acc[q*4+0] += a4.x*va + b4.x*vb + c4.x*vc + d4.x*vd;
                    acc[q*4+1] += a4.y*va + b4.y*vb + c4.y*vc + d4.y*vd;
                    acc[q*4+2] += a4.z*va + b4.z*vb + c4.z*vc + d4.z*vd;
                    acc[q*4+3] += a4.w*va + b4.w*vb + c4.w*vc + d4.w*vd;
                }
            }
            for (; cc < lim; cc++) {
                float v = __ldg(ibase + (size_t)(cb + cc)*HW);
                const float4* wq = (const float4*)&sw[cc*88 + cog*44];
#pragma unroll
                for (int q = 0; q < 11; q++) {
                    float4 wv = wq[q];
                    acc[q*4+0] += wv.x*v; acc[q*4+1] += wv.y*v;
                    acc[q*4+2] += wv.z*v; acc[q*4+3] += wv.w*v;
                }
            }
        }
    }
    if (pv) {
        float* ob = m.out[l] + (size_t)b*88*HW + pix;
#pragma unroll
        for (int j = 0; j < 44; j++)
            ob[(size_t)(cog*44 + j)*HW] = acc[j];
    }
}

// ---------------------------------------------------------------------------
// fused BiFPN sep-conv: fuse -> depthwise 3x3 -> pointwise 88x88 + ReLU
// ---------------------------------------------------------------------------
#define SP 260
#define CK 22

__global__ __launch_bounds__(256) void sep_k(
    const float* __restrict__ x, const float* __restrict__ y,
    const float* __restrict__ z, const float* __restrict__ fw,
    int mode, const float* __restrict__ dww, const float* __restrict__ pww,
    const float* __restrict__ pwb, float* __restrict__ out, int H)
{
    __shared__ __align__(16) float fbuf[CK*SP];
    __shared__ __align__(16) float dwbuf[CK*128];
    __shared__ __align__(16) float swp[CK*88];
    int W = H, HW = H*W;
    int lw = 31 - __clz(W);
    int tid = threadIdx.x;
    int b = blockIdx.y;
    int p0 = blockIdx.x*128;
    int qlo = max(0, p0 - W - 1);
    int qhi = min(HW, p0 + 128 + W + 1);
    int span = qhi - qlo;

    float w0f = fmaxf(__ldg(fw + 0), 0.f);
    float w1f = fmaxf(__ldg(fw + 1), 0.f);
    float w2f = (mode == 1) ? fmaxf(__ldg(fw + 2), 0.f) : 0.f;
    float sn = 1.f / (w0f + w1f + w2f + 1e-4f);

    int px = tid & 127, cog = tid >> 7;
    bool pv = (p0 + px) < HW;

    float acc[44];
#pragma unroll
    for (int j = 0; j < 44; j++) acc[j] = __ldg(pwb + cog*44 + j);

    gdep();

    for (int cb = 0; cb < 88; cb += CK) {
        __syncthreads();
        for (int i = tid; i < CK*88; i += 256) {
            int cc = i / 88, co = i - cc*88;
            swp[cc*88 + co] = __ldg(pww + co*88 + cb + cc);
        }
        int tot = CK*span;
        for (int i = tid; i < tot; i += 256) {
            int cc = i / span;
            int qq = qlo + (i - cc*span);
            int ch = cb + cc;
            size_t xb = ((size_t)b*88 + ch)*HW;
            int h = qq >> lw, w = qq & (W-1);
            float xv = __ldg(x + xb + qq);
            float val;
            if (mode == 0) {
                float yv = __ldg(y + ((size_t)b*88 + ch)*(HW>>2)
                                   + (h>>1)*(W>>1) + (w>>1));
                val = (w0f*xv + w1f*yv)*sn;
            } else {
                const float* zp = z + ((size_t)b*88 + ch)*((size_t)HW<<2)
                                    + (size_t)(2*h)*(2*W) + 2*w;
                float m4 = fmaxf(fmaxf(__ldg(zp), __ldg(zp+1)),
                                 fmaxf(__ldg(zp+2*W), __ldg(zp+2*W+1)));
                if (mode == 1) {
                    float yv = __ldg(y + xb + qq);
                    val = (w0f*xv + w1f*yv + w2f*m4)*sn;
                } else {
                    val = (w0f*xv + w1f*m4)*sn;
                }
            }
            fbuf[cc*SP + (qq - qlo)] = val;
        }
        __syncthreads();
        int v = tid;
#pragma unroll
        for (int r = 0; r < 11; r++, v += 256) {
            int cc = v >> 7, pp = v & 127;
            int p = p0 + pp;
            float sres = 0.f;
            if (p < HW) {
                int h = p >> lw, w = p & (W-1);
                const float* wp = dww + (cb + cc)*9;
                const float* fr = &fbuf[cc*SP];
                int qc = p - qlo;
                bool hu = h > 0, hd = h < H-1, wl = w > 0, wr = w < W-1;
                sres = __ldg(wp+4)*fr[qc];
                if (hu) { sres += __ldg(wp+1)*fr[qc-W];
                          if (wl) sres += __ldg(wp+0)*fr[qc-W-1];
                          if (wr) sres += __ldg(wp+2)*fr[qc-W+1]; }
                if (wl)   sres += __ldg(wp+3)*fr[qc-1];
                if (wr)   sres += __ldg(wp+5)*fr[qc+1];
                if (hd) { sres += __ldg(wp+7)*fr[qc+W];
                          if (wl) sres += __ldg(wp+6)*fr[qc+W-1];
                          if (wr) sres += __ldg(wp+8)*fr[qc+W+1]; }
            }
            dwbuf[cc*128 + pp] = sres;
        }
        __syncthreads();
        if (pv) {
#pragma unroll
            for (int cc = 0; cc < CK; cc++) {
                float vv = dwbuf[cc*128 + px];
                const float4* wq = (const float4*)&swp[cc*88 + cog*44];
#pragma unroll
                for (int q = 0; q < 11; q++) {
                    float4 wv = wq[q];
                    acc[q*4+0] += wv.x*vv; acc[q*4+1] += wv.y*vv;
                    acc[q*4+2] += wv.z*vv; acc[q*4+3] += wv.w*vv;
                }
            }
        }
    }
    if (pv) {
        float* ob = out + (size_t)b*88*HW + p0 + px;
#pragma unroll
        for (int j = 0; j < 44; j++)
            ob[(size_t)(cog*44 + j)*HW] = fmaxf(acc[j], 0.f);
    }
}

// ---------------------------------------------------------------------------
// batched conv3x3, CI=88. 44 co per block (blockIdx.z); 2px x 11co/thread.
// 4 blocks/SM.
// ---------------------------------------------------------------------------
struct ConvMap {
    const float* in[10]; float* out[10];
    const float* wgt[10]; const float* bias[10];
    int H[10]; int npb[10]; int loff[10];
    int blkOff[11]; int nent;
};

__global__ __launch_bounds__(256, 4) void conv3x3_k(ConvMap m, int CO, int mode,
                                                    int out_ch, float* headOut)
{
    __shared__ __align__(16) float sw[8*44*12];
    int tid = threadIdx.x;
    int bx = blockIdx.x;
    int l = 0;
    while (l + 1 < m.nent && bx >= m.blkOff[l+1]) l++;
    int local = bx - m.blkOff[l];
    int npb = m.npb[l];
    int b = local / npb, pixblk = local - b*npb;
    int H = m.H[l], W = H, HW = H*W;
    int lw = 31 - __clz(W);
    int pairIdx = tid & 63;
    int cog = tid >> 6;
    int px0 = pixblk*128 + pairIdx*2;
    int cb0 = blockIdx.z * 44;
    bool pv = px0 < HW;
    int h = px0 >> lw, w = px0 & (W-1);
    const float* wgt = m.wgt[l];
    const float* bias = m.bias[l];

    float acc[22];
#pragma unroll
    for (int j = 0; j < 11; j++) {
        int co = cb0 + cog*11 + j;
        float bv = (co < CO) ? __ldg(&bias[co]) : 0.f;
        acc[j] = bv; acc[11 + j] = bv;
    }

    gdep();

    const float* ib = m.in[l] + (size_t)b*88*HW;
    bool hu = h > 0, hd = h < H-1, wl = w > 0, wr = w + 2 < W;

    for (int cb = 0; cb < 88; cb += 8) {
        __syncthreads();
        for (int i = tid; i < 44*8*9; i += 256) {
            int co = i / 72; int r = i % 72; int ci = r / 9; int tap = r % 9;
            int gco = cb0 + co;
            sw[(ci*44 + co)*12 + tap] =
                (gco < CO) ? __ldg(&wgt[((size_t)gco*88 + cb + ci)*9 + tap]) : 0.f;
        }
        __syncthreads();
        if (pv) {
            for (int ci = 0; ci < 8; ci++) {
                const float* ip = ib + (size_t)(cb + ci)*HW + px0;
                float tm = (hu && wl) ? ip[-W-1] : 0.f;
                float ta =  hu        ? ip[-W]   : 0.f;
                float tb =  hu        ? ip[-W+1] : 0.f;
                float tc = (hu && wr) ? ip[-W+2] : 0.f;
                float mm =  wl        ? ip[-1]   : 0.f;
                float ma =              ip[0];
                float mb =              ip[1];
                float mc =  wr        ? ip[2]    : 0.f;
                float bm = (hd && wl) ? ip[W-1]  : 0.f;
                float ba =  hd        ? ip[W]    : 0.f;
                float bb =  hd        ? ip[W+1]  : 0.f;
                float bc = (hd && wr) ? ip[W+2]  : 0.f;
                const float* swc = &sw[(ci*44 + cog*11)*12];
#pragma unroll
                for (int j = 0; j < 11; j++) {
                    const float4* wq = (const float4*)(swc + j*12);
                    float4 wa = wq[0];
                    float4 wb4 = wq[1];
                    float  w8 = swc[j*12 + 8];
                    acc[j]      += wa.x*tm + wa.y*ta + wa.z*tb
                                 + wa.w*mm + wb4.x*ma + wb4.y*mb
                                 + wb4.z*bm + wb4.w*ba + w8*bb;
                    acc[11 + j] += wa.x*ta + wa.y*tb + wa.z*tc
                                 + wa.w*ma + wb4.x*mb + wb4.y*mc
                                 + wb4.z*ba + wb4.w*bb + w8*bc;
                }
            }
        }
    }

    if (!pv) return;

    if (mode == 0) {
        float* ob = m.out[l] + (size_t)b*88*HW + px0;
#pragma unroll
        for (int j = 0; j < 11; j++) {
            int co = cb0 + cog*11 + j;
            ob[(size_t)co*HW]     = fmaxf(acc[j], 0.f);
            ob[(size_t)co*HW + 1] = fmaxf(acc[11 + j], 0.f);
        }
    } else {
#pragma unroll
        for (int j = 0; j < 11; j++) {
            int co = cb0 + cog*11 + j;
            if (co < CO) {
                int a = co / out_ch, k = co % out_ch;
                float v0 = acc[j], v1 = acc[11 + j];
                if (mode == 2) {
                    v0 = 1.f / (1.f + __expf(-v0));
                    v1 = 1.f / (1.f + __expf(-v1));
                }
                size_t base = ((size_t)b*ATOT + m.loff[l] + (size_t)px0*9 + a)*out_ch + k;
                headOut[base] = v0;
                headOut[base + (size_t)9*out_ch] = v1;
            }
        }
    }
}

// ---------------------------------------------------------------------------
// anchors
// ---------------------------------------------------------------------------
__global__ void anchors_k(float* __restrict__ out)
{
    int i = blockIdx.x*256 + threadIdx.x;
    if (i >= ATOT) return;
    const int off[6]    = {0,36864,46080,48384,48960,49104};
    const int fsA[5]    = {64,32,16,8,4};
    const int strideA[5]= {8,16,32,64,128};
    const int asizeA[5] = {32,64,128,256,512};
    int l = 0;
    while (l < 4 && i >= off[l+1]) l++;
    int j = i - off[l];
    int fs = fsA[l];
    int pix = j / 9, a = j % 9;
    int r = a / 3, sc = a % 3;
    float scale = exp2f((float)sc * (1.f/3.f));
    float sr = (r == 0) ? 0.70710678118654752f : (r == 1 ? 1.f : 1.41421356237309505f);
    float wsz = (float)asizeA[l] * scale / sr;
    float hsz = (float)asizeA[l] * scale * sr;
    int y = pix / fs, x = pix % fs;
    float cx = (x + 0.5f) * (float)strideA[l];
    float cy = (y + 0.5f) * (float)strideA[l];
    out[(size_t)i*4 + 0] = cx - wsz*0.5f;
    out[(size_t)i*4 + 1] = cy - hsz*0.5f;
    out[(size_t)i*4 + 2] = cx + wsz*0.5f;
    out[(size_t)i*4 + 3] = cy + hsz*0.5f;
}

// ---------------------------------------------------------------------------
// PDL launch helper with explicit stream (fallback to plain launch)
// ---------------------------------------------------------------------------
static inline void launchPDL(const void* fn, dim3 grid, dim3 block, void** args,
                             cudaStream_t st)
{
    cudaLaunchConfig_t cfg = {};
    cfg.gridDim = grid; cfg.blockDim = block;
    cfg.dynamicSmemBytes = 0; cfg.stream = st;
    cudaLaunchAttribute at[1];
    at[0].id = cudaLaunchAttributeProgrammaticStreamSerialization;
    at[0].val.programmaticStreamSerializationAllowed = 1;
    cfg.attrs = at; cfg.numAttrs = 1;
    if (cudaLaunchKernelExC(&cfg, fn, args) != cudaSuccess) {
        cudaGetLastError();
        cfg.numAttrs = 0;
        cudaLaunchKernelExC(&cfg, fn, args);
    }
}

// ---------------------------------------------------------------------------
// host driver
// ---------------------------------------------------------------------------
extern "C" void kernel_launch(void* const* d_in, const int* in_sizes, int n_in,
                              void* d_out, int out_size)
{
    (void)in_sizes; (void)n_in; (void)out_size;
    const float* c[5]  = { (const float*)d_in[0], (const float*)d_in[3], (const float*)d_in[6],
                           (const float*)d_in[9], (const float*)d_in[12] };
    const float* lw[5] = { (const float*)d_in[1], (const float*)d_in[4], (const float*)d_in[7],
                           (const float*)d_in[10], (const float*)d_in[13] };
    const float* lb[5] = { (const float*)d_in[2], (const float*)d_in[5], (const float*)d_in[8],
                           (const float*)d_in[11], (const float*)d_in[14] };
    const float* bif_dw = (const float*)d_in[15];
    const float* bif_pw = (const float*)d_in[16];
    const float* bif_pb = (const float*)d_in[17];
    const float* bif_f2 = (const float*)d_in[18];
    const float* bif_f3 = (const float*)d_in[19];
    const float* reg_tw = (const float*)d_in[20];
    const float* reg_tb = (const float*)d_in[21];
    const float* reg_ow = (const float*)d_in[22];
    const float* reg_ob = (const float*)d_in[23];
    const float* cls_tw = (const float*)d_in[24];
    const float* cls_tb = (const float*)d_in[25];
    const float* cls_ow = (const float*)d_in[26];
    const float* cls_ob = (const float*)d_in[27];
    float* outp = (float*)d_out;

    float *A[5], *Bq[5], *T4, *T5, *T6, *HA, *HB;
    cudaGetSymbolAddress((void**)&A[0], g_P3);
    cudaGetSymbolAddress((void**)&A[1], g_P4);
    cudaGetSymbolAddress((void**)&A[2], g_P5);
    cudaGetSymbolAddress((void**)&A[3], g_P6);
    cudaGetSymbolAddress((void**)&A[4], g_P7);
    cudaGetSymbolAddress((void**)&Bq[0], g_Q3);
    cudaGetSymbolAddress((void**)&Bq[1], g_Q4);
    cudaGetSymbolAddress((void**)&Bq[2], g_Q5);
    cudaGetSymbolAddress((void**)&Bq[3], g_Q6);
    cudaGetSymbolAddress((void**)&Bq[4], g_Q7);
    cudaGetSymbolAddress((void**)&T4, g_T4);
    cudaGetSymbolAddress((void**)&T5, g_T5);
    cudaGetSymbolAddress((void**)&T6, g_T6);
    cudaGetSymbolAddress((void**)&HA, g_HA);
    cudaGetSymbolAddress((void**)&HB, g_HB);

    // fork stream for the cls chain (created per call; NOT destroyed while
    // the harness's capture may still be active; no device memory involved)
    cudaStream_t s1 = 0;
    cudaEvent_t eFork = 0, eJoin = 0;
    bool forked =
        (cudaStreamCreateWithFlags(&s1, cudaStreamNonBlocking) == cudaSuccess) &&
        (cudaEventCreateWithFlags(&eFork, cudaEventDisableTiming) == cudaSuccess) &&
        (cudaEventCreateWithFlags(&eJoin, cudaEventDisableTiming) == cudaSuccess);
    if (!forked) { cudaGetLastError(); s1 = 0; }

    // anchors (independent)
    anchors_k<<<(ATOT + 255)/256, 256>>>(outp + ANC_BASE);

    // ---- laterals ----
    float* cur[5] = { A[0], A[1], A[2], A[3], A[4] };
    {
        PwMap pm; pm.nent = 5;
        int acc = 0;
        for (int l = 0; l < 5; l++) {
            pm.in[l] = c[l]; pm.wgt[l] = lw[l]; pm.bias[l] = lb[l];
            pm.out[l] = cur[l];
            pm.CI[l] = g_LCI[l]; pm.HW[l] = g_LHW[l]; pm.npb[l] = g_NPB[l];
            pm.blkOff[l] = acc; acc += g_NPB[l]*BATCH;
        }
        pm.blkOff[5] = acc;
        pw_k<<<acc, 256>>>(pm);
    }

    // ---- BiFPN stages: 8 fused sep-conv launches each, PDL-chained ----
    for (int s = 0; s < 3; s++) {
        const float* dws = bif_dw + (size_t)s*8*88*9;
        const float* pws = bif_pw + (size_t)s*8*88*88;
        const float* pbs = bif_pb + (size_t)s*8*88;
        const float* f2  = bif_f2 + (size_t)s*10;
        const float* f3  = bif_f3 + (size_t)s*9;

        auto sep = [&](int idx, int lvl, int mode, const float* x, const float* y,
                       const float* z, const float* fwp, float* dst) {
            int H = g_LH[lvl];
            dim3 grid((g_LHW[lvl] + 127)/128, BATCH);
            const float* dwwp = dws + idx*88*9;
            const float* pwwp = pws + (size_t)idx*88*88;
            const float* pbp  = pbs + idx*88;
            void* args[] = { (void*)&x, (void*)&y, (void*)&z, (void*)&fwp,
                             (void*)&mode, (void*)&dwwp, (void*)&pwwp,
                             (void*)&pbp, (void*)&dst, (void*)&H };
            launchPDL((const void*)sep_k, grid, dim3(256,1,1), args, 0);
        };
        auto oth = [&](int l) { return (cur[l] == A[l]) ? Bq[l] : A[l]; };

        sep(0, 3, 0, cur[3], cur[4], nullptr, f2 + 0, T6);
        sep(1, 2, 0, cur[2], T6,     nullptr, f2 + 2, T5);
        sep(2, 1, 0, cur[1], T5,     nullptr, f2 + 4, T4);
        float* n0 = oth(0); sep(3, 0, 0, cur[0], T4, nullptr, f2 + 6, n0); cur[0] = n0;
        float* n1 = oth(1); sep(4, 1, 1, cur[1], T4, cur[0], f3 + 0, n1); cur[1] = n1;
        float* n2 = oth(2); sep(5, 2, 1, cur[2], T5, cur[1], f3 + 3, n2); cur[2] = n2;
        float* n3 = oth(3); sep(6, 3, 1, cur[3], T6, cur[2], f3 + 6, n3); cur[3] = n3;
        float* n4 = oth(4); sep(7, 4, 2, cur[4], nullptr, cur[3], f2 + 8, n4); cur[4] = n4;
    }

    // ---- fork: cls chain on s1, reg chain on stream 0 ----
    if (forked) {
        cudaEventRecord(eFork, 0);
        cudaStreamWaitEvent(s1, eFork, 0);
    }

    auto launchConv = [&](ConvMap& cm, dim3 grid, int CO, int mode, int out_ch,
                          float* headOut, cudaStream_t st) {
        void* args[] = { (void*)&cm, (void*)&CO, (void*)&mode,
                         (void*)&out_ch, (void*)&headOut };
        launchPDL((const void*)conv3x3_k, grid, dim3(256,1,1), args, st);
    };

    // per-head chain: 4 towers + output conv
    auto runHead = [&](int head, const float* tw, const float* tb,
                       const float* ow, const float* ob,
                       int CO, int out_ch, int mode, float* obase,
                       int zout, cudaStream_t st) {
        for (int i = 0; i < 4; i++) {
            ConvMap cm; cm.nent = 5;
            int acc = 0;
            float* dstbuf = ((i & 1) ? HB : HA) + (size_t)head*HEADBUF;
            float* srcbuf = ((i & 1) ? HA : HB) + (size_t)head*HEADBUF;
            for (int l = 0; l < 5; l++) {
                cm.H[l] = g_LH[l]; cm.npb[l] = g_NPB[l]; cm.loff[l] = 0;
                cm.blkOff[l] = acc; acc += g_NPB[l]*BATCH;
                cm.in[l]  = (i == 0) ? (const float*)cur[l]
                                     : (const float*)(srcbuf + g_BASE[l]);
                cm.out[l] = dstbuf + g_BASE[l];
                cm.wgt[l]  = tw + (size_t)i*88*88*9;
                cm.bias[l] = tb + i*88;
            }
            cm.blkOff[5] = acc;
            launchConv(cm, dim3(acc, 1, 2), 88, 0, 0, nullptr, st);
        }
        // output conv reads HB region (i=3 wrote HB)
        ConvMap cm; cm.nent = 5;
        int acc = 0;
        for (int l = 0; l < 5; l++) {
            cm.H[l] = g_LH[l]; cm.npb[l] = g_NPB[l]; cm.loff[l] = g_LOFF[l];
            cm.blkOff[l] = acc; acc += g_NPB[l]*BATCH;
            cm.in[l] = HB + (size_t)head*HEADBUF + g_BASE[l];
            cm.out[l] = nullptr;
            cm.wgt[l] = ow; cm.bias[l] = ob;
        }
        cm.blkOff[5] = acc;
        launchConv(cm, dim3(acc, 1, zout), CO, mode, out_ch, obase, st);
    };

    runHead(0, reg_tw, reg_tb, reg_ow, reg_ob,  36,  4, 1, outp + REG_BASE, 1, 0);
    runHead(1, cls_tw, cls_tb, cls_ow, cls_ob, 810, 90, 2, outp,           19,
            forked ? s1 : 0);

    // ---- join ----
    if (forked) {
        cudaEventRecord(eJoin, s1);
        cudaStreamWaitEvent(0, eJoin, 0);
    }
}